// round 13
// baseline (speedup 1.0000x reference)
#include <cuda_runtime.h>
#include <cuda_fp16.h>
#include <math.h>

// ---------------- problem constants ----------------
#define BB    32
#define HH    28
#define WW    28
#define CC    192
#define HEADS 6
#define HD    32
#define KW    3
#define K2    9
#define NTOK  (BB*HH*WW)          // 25088
#define HID   576
#define ACOLS (K2*K2*HEADS)       // 486
#define MVA   (CC + ACOLS)        // 678 fused V|A output cols
#define MVA_PAD 704
#define SCALE 0.17677669529663687f
#define EPSLN 1e-5f

// transposed-weight pool (halves), layout [M][K]
#define WOFF_VA 0
#define WOFF_P  (MVA_PAD*CC)              // 135168
#define WOFF_1  (WOFF_P + CC*CC)          // 172032
#define WOFF_2  (WOFF_1 + HID*CC)         // 282624
#define WTOT    (WOFF_2 + CC*HID)         // 393216
#define N_WCONV (CC*MVA + CC*CC + CC*HID + HID*CC)  // 388224 real elements

// ---------------- scratch (static device globals; no allocs) ----------------
__device__ __half g_wh [WTOT];            // zero-init; VA pad rows never written
__device__ float  g_bva[MVA_PAD];
__device__ __half g_ln1[(size_t)NTOK*CC];
__device__ float  g_va [(size_t)NTOK*MVA];
__device__ __half g_tmp[(size_t)NTOK*CC];
__device__ float  g_x2 [(size_t)NTOK*CC];
__device__ __half g_ln2[(size_t)NTOK*CC];
__device__ __half g_h1 [(size_t)NTOK*HID];

// ---------------- weight fp32 -> fp16 transpose pack ----------------
__global__ void wconv_kernel(const float* __restrict__ Wv, const float* __restrict__ Wa,
                             const float* __restrict__ Wp, const float* __restrict__ W1,
                             const float* __restrict__ W2, __half* __restrict__ out)
{
    int i = blockIdx.x * 256 + threadIdx.x;
    if (i >= N_WCONV) return;
    const int SZ_VA = CC*MVA;       // 130176
    const int SZ_P  = CC*CC;        // 36864
    const int SZ_1  = CC*HID;       // 110592
    if (i < SZ_VA) {
        int m = i / CC, k = i - m*CC;         // m in [0,678)
        float v = (m < CC) ? Wv[k*CC + m] : Wa[k*ACOLS + (m - CC)];
        out[WOFF_VA + m*CC + k] = __float2half_rn(v);
    } else if (i < SZ_VA + SZ_P) {
        int e = i - SZ_VA;
        int m = e / CC, k = e - m*CC;
        out[WOFF_P + m*CC + k] = __float2half_rn(Wp[k*CC + m]);
    } else if (i < SZ_VA + SZ_P + SZ_1) {
        int e = i - SZ_VA - SZ_P;
        int m = e / CC, k = e - m*CC;         // m in [0,576)
        out[WOFF_1 + m*CC + k] = __float2half_rn(W1[k*HID + m]);
    } else {
        int e = i - SZ_VA - SZ_P - SZ_1;
        int m = e / HID, k = e - m*HID;       // m in [0,192), k in [0,576)
        out[WOFF_2 + m*HID + k] = __float2half_rn(W2[k*CC + m]);
    }
}

__global__ void bias_fuse_kernel(const float* __restrict__ ba, float* __restrict__ bva)
{
    int i = blockIdx.x * 256 + threadIdx.x;
    if (i < MVA_PAD) bva[i] = (i >= CC && i < MVA) ? ba[i - CC] : 0.f;
}

// ---------------- LayerNorm: one warp per token, half output ----------------
__global__ void ln_kernel(const float* __restrict__ x,
                          const float* __restrict__ g,
                          const float* __restrict__ b,
                          __half* __restrict__ out)
{
    int warp = (blockIdx.x * blockDim.x + threadIdx.x) >> 5;
    int lane = threadIdx.x & 31;
    if (warp >= NTOK) return;
    const float* row = x + (size_t)warp * CC;
    float vals[6];
    float s = 0.f;
    #pragma unroll
    for (int i = 0; i < 6; i++) { vals[i] = row[lane + 32*i]; s += vals[i]; }
    #pragma unroll
    for (int o = 16; o > 0; o >>= 1) s += __shfl_xor_sync(0xffffffffu, s, o);
    float mean = s * (1.f/CC);
    float vs = 0.f;
    #pragma unroll
    for (int i = 0; i < 6; i++) { float d = vals[i]-mean; vs += d*d; }
    #pragma unroll
    for (int o = 16; o > 0; o >>= 1) vs += __shfl_xor_sync(0xffffffffu, vs, o);
    float r = rsqrtf(vs * (1.f/CC) + EPSLN);
    __half* orow = out + (size_t)warp * CC;
    #pragma unroll
    for (int i = 0; i < 6; i++) {
        int c = lane + 32*i;
        orow[c] = __float2half_rn((vals[i]-mean) * r * g[c] + b[c]);
    }
}

// ---------------- FP16 GEMM: 128x64 tile, 4-stage cp.async, 3 CTAs/SM ----------------
#define SA_ST 40                      // halves; pad -> conflict-free LDS.32
#define SB_ST 40
#define SA_SZ (128*SA_ST)             // 5120 halves / stage
#define SB_SZ (64*SB_ST)              // 2560 halves / stage
#define STG_H (SA_SZ + SB_SZ)         // 7680
#define NSTG  4
#define GEMM_SMEM (NSTG*STG_H*2)      // 61440 bytes

__device__ __forceinline__ void cp16(unsigned dst, const void* src) {
    asm volatile("cp.async.ca.shared.global [%0], [%1], 16;" :: "r"(dst), "l"(src));
}
__device__ __forceinline__ void cp_commit() {
    asm volatile("cp.async.commit_group;");
}

// EPI: 0 bias float out, 1 bias+gelu half out, 2 bias+residual float out
template<int EPI, typename OutT>
__global__ __launch_bounds__(256, 3)
void gemm_f16_kernel(const __half* __restrict__ A,
                     const __half* __restrict__ Bt,   // [M_pad, Kd]
                     const float* __restrict__ bias,
                     const float* __restrict__ res,
                     OutT* __restrict__ out,
                     int Kd, int M)
{
    extern __shared__ __half smem[];
    const unsigned smem_base = (unsigned)__cvta_generic_to_shared(smem);
    const unsigned short* smem_us = (const unsigned short*)smem;

    const int tid  = threadIdx.x;
    const int lane = tid & 31;
    const int w    = tid >> 5;
    const int wr   = w & 3;        // 32 rows each
    const int wc   = w >> 2;       // 32 cols each
    const int gid  = lane >> 2;
    const int tig  = lane & 3;
    const int row0 = blockIdx.y * 128;
    const int col0 = blockIdx.x * 64;

    float acc[2][4][4];
    #pragma unroll
    for (int mt = 0; mt < 2; mt++)
        #pragma unroll
        for (int nt = 0; nt < 4; nt++)
            #pragma unroll
            for (int i = 0; i < 4; i++) acc[mt][nt][i] = 0.f;

    const int nk = Kd / 32;

    auto issue_stage = [&](int s) {
        int kb = s * 32;
        unsigned base = smem_base + (unsigned)((s % NSTG) * STG_H * 2);
        // A: 128 rows x 32 halves = 512 cp16 (8 halves each) -> 2 per thread
        #pragma unroll
        for (int i = 0; i < 2; i++) {
            int f = tid + 256*i;
            int r = f >> 2, kq = (f & 3) * 8;
            cp16(base + (unsigned)((r*SA_ST + kq)*2),
                 &A[(size_t)(row0 + r) * Kd + kb + kq]);
        }
        // B^T: 64 rows x 32 halves = 256 cp16 -> 1 per thread
        {
            int r = tid >> 2, kq = (tid & 3) * 8;
            cp16(base + (unsigned)(SA_SZ*2) + (unsigned)((r*SB_ST + kq)*2),
                 &Bt[(size_t)(col0 + r) * Kd + kb + kq]);
        }
    };

    issue_stage(0); cp_commit();
    if (nk > 1) { issue_stage(1); cp_commit(); }
    if (nk > 2) { issue_stage(2); cp_commit(); }

    for (int it = 0; it < nk; it++) {
        // groups issued = min(it+3, nk); group `it` must be complete:
        // allowable pending = min(2, nk-1-it)
        int rem = nk - 1 - it;
        if (rem >= 2)      asm volatile("cp.async.wait_group 2;" ::: "memory");
        else if (rem == 1) asm volatile("cp.async.wait_group 1;" ::: "memory");
        else               asm volatile("cp.async.wait_group 0;" ::: "memory");
        __syncthreads();
        if (it + 3 < nk) { issue_stage(it + 3); cp_commit(); }

        const unsigned short* cA = smem_us + (it % NSTG) * STG_H;
        const unsigned short* cB = cA + SA_SZ;
        #pragma unroll
        for (int ks = 0; ks < 2; ks++) {
            const int k0 = ks * 16;
            unsigned af[2][4];
            #pragma unroll
            for (int mt = 0; mt < 2; mt++) {
                int r = wr*32 + mt*16 + gid;
                af[mt][0] = *(const unsigned*)&cA[ r     *SA_ST + k0 + tig*2    ];
                af[mt][1] = *(const unsigned*)&cA[(r + 8)*SA_ST + k0 + tig*2    ];
                af[mt][2] = *(const unsigned*)&cA[ r     *SA_ST + k0 + tig*2 + 8];
                af[mt][3] = *(const unsigned*)&cA[(r + 8)*SA_ST + k0 + tig*2 + 8];
            }
            unsigned bf[4][2];
            #pragma unroll
            for (int nt = 0; nt < 4; nt++) {
                int c = wc*32 + nt*8 + gid;
                bf[nt][0] = *(const unsigned*)&cB[c*SB_ST + k0 + tig*2    ];
                bf[nt][1] = *(const unsigned*)&cB[c*SB_ST + k0 + tig*2 + 8];
            }
            #pragma unroll
            for (int mt = 0; mt < 2; mt++)
                #pragma unroll
                for (int nt = 0; nt < 4; nt++) {
                    asm volatile(
                      "mma.sync.aligned.m16n8k16.row.col.f32.f16.f16.f32 "
                      "{%0,%1,%2,%3},{%4,%5,%6,%7},{%8,%9},{%0,%1,%2,%3};"
                      : "+f"(acc[mt][nt][0]), "+f"(acc[mt][nt][1]),
                        "+f"(acc[mt][nt][2]), "+f"(acc[mt][nt][3])
                      : "r"(af[mt][0]), "r"(af[mt][1]),
                        "r"(af[mt][2]), "r"(af[mt][3]),
                        "r"(bf[nt][0]), "r"(bf[nt][1]));
                }
        }
    }

    // epilogue
    #pragma unroll
    for (int mt = 0; mt < 2; mt++) {
        #pragma unroll
        for (int nt = 0; nt < 4; nt++) {
            int r0  = row0 + wr*32 + mt*16 + gid;
            int col = col0 + wc*32 + nt*8 + tig*2;
            if (col < M) {
                float2 bb = make_float2(0.f, 0.f);
                if (bias) bb = *(const float2*)&bias[col];
                #pragma unroll
                for (int half_i = 0; half_i < 2; half_i++) {
                    int row = r0 + half_i*8;
                    float vx = acc[mt][nt][half_i*2    ] + bb.x;
                    float vy = acc[mt][nt][half_i*2 + 1] + bb.y;
                    if (EPI == 1) {
                        vx = 0.5f * vx * (1.0f + erff(vx * 0.70710678118654752f));
                        vy = 0.5f * vy * (1.0f + erff(vy * 0.70710678118654752f));
                        *(__half2*)&out[(size_t)row * M + col] = __floats2half2_rn(vx, vy);
                    } else if (EPI == 2) {
                        float2 rr = *(const float2*)&res[(size_t)row * M + col];
                        *(float2*)&((float*)out)[(size_t)row * M + col] =
                            make_float2(vx + rr.x, vy + rr.y);
                    } else {
                        *(float2*)&((float*)out)[(size_t)row * M + col] =
                            make_float2(vx, vy);
                    }
                }
            }
        }
    }
}

// ---------------- fused outlook attention + fold (reads fused va buffer) ----------------
#define PR_ROW 12
#define PR_HEAD (K2*PR_ROW)            // 108
#define PR_WARP (HEADS*PR_HEAD)        // 648

__global__ void attn_fold_kernel(const float* __restrict__ va,
                                 __half* __restrict__ tmp)
{
    __shared__ float probs[8][PR_WARP];
    int warp = threadIdx.x >> 5;
    int lane = threadIdx.x & 31;
    int t = blockIdx.x * 8 + warp;
    int b  = t / (HH*WW);
    int pq = t % (HH*WW);
    int p = pq / WW, q = pq % WW;

    // ---- phase A: 54 softmax rows over 27 lanes (2 each) ----
    if (lane < 27) {
        #pragma unroll
        for (int rep = 0; rep < 2; rep++) {
            int rr = lane + rep*27;
            int head = rr / K2;
            int i    = rr - head*K2;
            int di = i / KW, dj = i - di*KW;
            int tp = p + 1 - di, tq = q + 1 - dj;
            float* dst = &probs[warp][head*PR_HEAD + i*PR_ROW];
            if ((unsigned)tp < (unsigned)HH && (unsigned)tq < (unsigned)WW) {
                int ts = (b*HH + tp) * WW + tq;
                const float* ar = va + (size_t)ts * MVA + CC + head*81 + i*K2;
                float vv[K2];
                float mx = -INFINITY;
                #pragma unroll
                for (int j = 0; j < K2; j++) { vv[j] = ar[j] * SCALE; mx = fmaxf(mx, vv[j]); }
                float s = 0.f;
                #pragma unroll
                for (int j = 0; j < K2; j++) { vv[j] = __expf(vv[j] - mx); s += vv[j]; }
                float inv = __fdividef(1.f, s);
                #pragma unroll
                for (int j = 0; j < K2; j++) dst[j] = vv[j] * inv;
            } else {
                #pragma unroll
                for (int j = 0; j < K2; j++) dst[j] = 0.f;
            }
        }
    }
    __syncwarp();

    // ---- phase B: window gather (v = first CC cols of va) ----
    int rowbase[5], coloff[5];
    unsigned rmask = 0, cmask = 0;
    #pragma unroll
    for (int d = 0; d < 5; d++) {
        int vp = p + d - 2, vq = q + d - 2;
        bool rok = (unsigned)vp < (unsigned)HH;
        bool cok = (unsigned)vq < (unsigned)WW;
        rowbase[d] = rok ? ((b*HH + vp) * WW) * MVA : 0;
        coloff[d]  = cok ? vq * MVA : 0;
        if (rok) rmask |= (1u << d);
        if (cok) cmask |= (1u << d);
    }

    for (int head = 0; head < HEADS; head++) {
        const int ch = head*HD + lane;
        float vr[25];
        #pragma unroll
        for (int dp = 0; dp < 5; dp++) {
            #pragma unroll
            for (int dq = 0; dq < 5; dq++) {
                bool ok = ((rmask >> dp) & 1u) && ((cmask >> dq) & 1u);
                vr[dp*5 + dq] = ok ? va[(size_t)(rowbase[dp] + coloff[dq] + ch)] : 0.f;
            }
        }
        const float* prh = &probs[warp][head*PR_HEAD];
        float acc = 0.f;
        #pragma unroll
        for (int i = 0; i < K2; i++) {
            int di = i / KW, dj = i - di*KW;
            const float4* rp = (const float4*)(prh + i*PR_ROW);
            float4 r0 = rp[0], r1 = rp[1];
            float  r2 = prh[i*PR_ROW + 8];
            float pr[K2] = {r0.x, r0.y, r0.z, r0.w, r1.x, r1.y, r1.z, r1.w, r2};
            const float* vb = &vr[(2 - di)*5 + (2 - dj)];
            #pragma unroll
            for (int j = 0; j < K2; j++) {
                int ei = j / KW, ej = j - ei*KW;
                acc = fmaf(pr[j], vb[ei*5 + ej], acc);
            }
        }
        tmp[(size_t)t * CC + ch] = __float2half_rn(acc);
    }
}

// ---------------- launcher ----------------
extern "C" void kernel_launch(void* const* d_in, const int* in_sizes, int n_in,
                              void* d_out, int out_size)
{
    const float* x     = (const float*)d_in[0];
    const float* ln1_g = (const float*)d_in[1];
    const float* ln1_b = (const float*)d_in[2];
    const float* Wv    = (const float*)d_in[3];
    const float* Wa    = (const float*)d_in[4];
    const float* ba    = (const float*)d_in[5];
    const float* Wp    = (const float*)d_in[6];
    const float* bp    = (const float*)d_in[7];
    const float* ln2_g = (const float*)d_in[8];
    const float* ln2_b = (const float*)d_in[9];
    const float* W1    = (const float*)d_in[10];
    const float* b1    = (const float*)d_in[11];
    const float* W2    = (const float*)d_in[12];
    const float* b2    = (const float*)d_in[13];
    float* out = (float*)d_out;

    __half *p_wh, *p_ln1, *p_tmp, *p_ln2, *p_h1;
    float  *p_bva, *p_va, *p_x2;
    cudaGetSymbolAddress((void**)&p_wh,  g_wh);
    cudaGetSymbolAddress((void**)&p_bva, g_bva);
    cudaGetSymbolAddress((void**)&p_ln1, g_ln1);
    cudaGetSymbolAddress((void**)&p_va,  g_va);
    cudaGetSymbolAddress((void**)&p_tmp, g_tmp);
    cudaGetSymbolAddress((void**)&p_x2,  g_x2);
    cudaGetSymbolAddress((void**)&p_ln2, g_ln2);
    cudaGetSymbolAddress((void**)&p_h1,  g_h1);

    cudaFuncSetAttribute((const void*)gemm_f16_kernel<0,float>,  cudaFuncAttributeMaxDynamicSharedMemorySize, GEMM_SMEM);
    cudaFuncSetAttribute((const void*)gemm_f16_kernel<1,__half>, cudaFuncAttributeMaxDynamicSharedMemorySize, GEMM_SMEM);
    cudaFuncSetAttribute((const void*)gemm_f16_kernel<2,float>,  cudaFuncAttributeMaxDynamicSharedMemorySize, GEMM_SMEM);

    const int RB = NTOK / 128;   // 196

    wconv_kernel<<<(N_WCONV + 255)/256, 256>>>(Wv, Wa, Wp, W1, W2, p_wh);
    bias_fuse_kernel<<<3, 256>>>(ba, p_bva);
    ln_kernel<<<NTOK/8, 256>>>(x, ln1_g, ln1_b, p_ln1);
    gemm_f16_kernel<0,float><<<dim3(11, RB), 256, GEMM_SMEM>>>(p_ln1, p_wh + WOFF_VA, p_bva, nullptr, p_va, CC, MVA);
    attn_fold_kernel<<<NTOK/8, 256>>>(p_va, p_tmp);
    gemm_f16_kernel<2,float><<<dim3(3, RB), 256, GEMM_SMEM>>>(p_tmp, p_wh + WOFF_P, bp, x, p_x2, CC, CC);
    ln_kernel<<<NTOK/8, 256>>>(p_x2, ln2_g, ln2_b, p_ln2);
    gemm_f16_kernel<1,__half><<<dim3(9, RB), 256, GEMM_SMEM>>>(p_ln2, p_wh + WOFF_1, b1, nullptr, p_h1, CC, HID);
    gemm_f16_kernel<2,float><<<dim3(3, RB), 256, GEMM_SMEM>>>(p_h1, p_wh + WOFF_2, b2, p_x2, out, HID, CC);
}